// round 16
// baseline (speedup 1.0000x reference)
#include <cuda_runtime.h>
#include <cuda_fp16.h>
#include <math.h>
#include <cstdint>

#define NNODES 10000
#define NEDGES 160000
#define DDIM   512
#define KTOT   1024
#define MTILE  96
#define MTILES 105
#define MPAD   (MTILE * MTILES)   // 10080
#define KCHUNK 64
#define NSTAGE 2
#define KSTEPS (KTOT / KCHUNK)    // 16
#define DEGCAP 128

// smem rows: 64 fp16 = 128B data + 16B pad -> stride 144B (conflict-free LDSM)
#define ROWB    144
#define A_TILEB (MTILE * ROWB)            // 13824
#define B_TILEB (128 * ROWB)              // 18432
#define OFF_AH  0
#define OFF_BH  (A_TILEB)
#define STAGE_BYTES (A_TILEB + B_TILEB)       // 32256
#define SMEM_TOTAL  (NSTAGE * STAGE_BYTES)    // 64512 -> 3 CTAs/SM

// fused kernel block ranges: gather first (dispatched first), then GEMM tiles
#define G_BLKS     2500                    // 2500 * 8 warps = 20000 (node,slice)
#define GEMM_BLKS  (MTILES * 4)            // 420
#define F_TOTAL    (G_BLKS + GEMM_BLKS)

// ---------------------------------------------------------------------------
// Device scratch
// ---------------------------------------------------------------------------
__device__ int    g_cursor[NNODES];
__device__ int    g_gather_done;
__device__ int    g_elist[(size_t)NNODES * DEGCAP];
__device__ __half g_Ah[(size_t)MPAD * KTOT];
__device__ __half g_Bh[(size_t)DDIM * KTOT];    // [n][k]

// ---------------------------------------------------------------------------
// helpers
// ---------------------------------------------------------------------------
__device__ __forceinline__ uint32_t smem_u32(const void* p) {
    uint32_t a;
    asm("{ .reg .u64 t; cvta.to.shared.u64 t, %1; cvt.u32.u64 %0, t; }"
        : "=r"(a) : "l"(p));
    return a;
}
#define CP16(sm, gm) \
    asm volatile("cp.async.cg.shared.global [%0], [%1], 16;" :: "r"(sm), "l"(gm))
#define CP_COMMIT() asm volatile("cp.async.commit_group;" ::: "memory")
#define CP_WAIT()   asm volatile("cp.async.wait_group 1;"  ::: "memory")

#define LDMX4(r0, r1, r2, r3, addr) \
    asm volatile("ldmatrix.sync.aligned.m8n8.x4.shared.b16 {%0,%1,%2,%3}, [%4];" \
        : "=r"(r0), "=r"(r1), "=r"(r2), "=r"(r3) : "r"(addr))

__device__ __forceinline__ void mma_fp16(float* c, const uint32_t* a,
                                         const uint32_t* b) {
    asm volatile(
        "mma.sync.aligned.m16n8k16.row.col.f32.f16.f16.f32 "
        "{%0,%1,%2,%3}, {%4,%5,%6,%7}, {%8,%9}, {%0,%1,%2,%3};"
        : "+f"(c[0]), "+f"(c[1]), "+f"(c[2]), "+f"(c[3])
        : "r"(a[0]), "r"(a[1]), "r"(a[2]), "r"(a[3]), "r"(b[0]), "r"(b[1]));
}

__device__ __forceinline__ void store_h4(float4 v, __half* p) {
    *(__half2*)(p)     = __floats2half2_rn(v.x, v.y);
    *(__half2*)(p + 2) = __floats2half2_rn(v.z, v.w);
}

// ---------------------------------------------------------------------------
// Kernel 1: fused prep — block-range dispatch:
//   [0, 625)        CSR bucket fill (atomics); block 0 also resets counter
//   [625, 5625)     x -> fp16 into A cols [512,1024)
//   [5625, 5705)    zero pad rows [NNODES, MPAD)
//   [5705, 6217)    B transpose (fp16)
// ---------------------------------------------------------------------------
#define P_FILL_BLKS 625
#define P_X_BLKS    5000
#define P_PAD_BLKS  80
#define P_B_BLKS    512
#define P_TOTAL (P_FILL_BLKS + P_X_BLKS + P_PAD_BLKS + P_B_BLKS)

__global__ __launch_bounds__(256) void prep_kernel(
    const void* __restrict__ ei,
    const float* __restrict__ x,
    const float* __restrict__ Wl, const float* __restrict__ Wr)
{
    __shared__ float ts[32][33];
    const int bb  = blockIdx.x;
    const int tid = threadIdx.x;

    if (bb < P_FILL_BLKS) {
        if (bb == 0 && tid == 0) g_gather_done = 0;   // replay-safe reset
        const int e = bb * 256 + tid;
        if (e >= NEDGES) return;
        const int* ei32 = (const int*)ei;
        int acc = 0;
#pragma unroll
        for (int j = 1; j < 32; j += 2) acc |= __ldg(ei32 + j);
        int src, dst;
        if (acc == 0) {
            const long long* e64 = (const long long*)ei;
            src = (int)e64[e];
            dst = (int)e64[NEDGES + e];
        } else {
            src = ei32[e];
            dst = ei32[NEDGES + e];
        }
        if ((unsigned)src >= NNODES || (unsigned)dst >= NNODES) return;
        const int pos = atomicAdd(&g_cursor[dst], 1);
        if (pos < DEGCAP) g_elist[(size_t)dst * DEGCAP + pos] = src;
    } else if (bb < P_FILL_BLKS + P_X_BLKS) {
        const int i = (bb - P_FILL_BLKS) * 256 + tid;
        const int row = i >> 7;
        const int g   = (i & 127) * 4;
        const float4 v = *(const float4*)(x + (size_t)row * DDIM + g);
        store_h4(v, g_Ah + (size_t)row * KTOT + DDIM + g);
    } else if (bb < P_FILL_BLKS + P_X_BLKS + P_PAD_BLKS) {
        const int i = (bb - P_FILL_BLKS - P_X_BLKS) * 256 + tid;
        const int row = NNODES + (i >> 8);
        const int g   = (i & 255) * 4;
        *(uint64_t*)(g_Ah + (size_t)row * KTOT + g) = 0ull;
    } else {
        const int tb = bb - P_FILL_BLKS - P_X_BLKS - P_PAD_BLKS;
        const int k0 = (tb >> 4) * 32;
        const int n0 = (tb & 15) * 32;
        const int r  = tid >> 3;
        const int c  = (tid & 7) * 4;

        const int k = k0 + r;
        const float4 v = (k < DDIM)
            ? *(const float4*)(Wl + (size_t)k * DDIM + n0 + c)
            : *(const float4*)(Wr + (size_t)(k - DDIM) * DDIM + n0 + c);
        ts[r][c + 0] = v.x; ts[r][c + 1] = v.y;
        ts[r][c + 2] = v.z; ts[r][c + 3] = v.w;
        __syncthreads();

        const int n = n0 + r;
        float4 w = make_float4(ts[c][r], ts[c + 1][r], ts[c + 2][r], ts[c + 3][r]);
        store_h4(w, g_Bh + (size_t)n * KTOT + k0 + c);
    }
}

// ---------------------------------------------------------------------------
// GEMM loader (x-half chunks first via rotated chunk index)
// ---------------------------------------------------------------------------
__device__ __forceinline__ void load_stage(
    uint32_t st, int k0, int mBase, int nBase, int tid)
{
    // 1792 16B-chunks: Ah 768 | Bh 1024 -> exactly 7 per thread
#pragma unroll
    for (int i = 0; i < 7; ++i) {
        const int c = tid + i * 256;
        uint32_t sm;
        const __half* gp;
        if (c < 768) {
            const int row = c >> 3;
            const int ch  = c & 7;
            sm = st + OFF_AH + row * ROWB + ch * 16;
            gp = g_Ah + (size_t)(mBase + row) * KTOT + k0 + ch * 8;
        } else {
            const int d   = c - 768;
            const int row = d >> 3;
            const int ch  = d & 7;
            sm = st + OFF_BH + row * ROWB + ch * 16;
            gp = g_Bh + (size_t)(nBase + row) * KTOT + k0 + ch * 8;
        }
        CP16(sm, gp);
    }
}

// ---------------------------------------------------------------------------
// Kernel 2: FUSED gather + GEMM.
//   blocks [0, G_BLKS): gather+mean for 4 nodes each (8 warps x (node,slice)),
//       then signal g_gather_done and reset own cursor entries.
//   blocks [G_BLKS, F_TOTAL): GEMM tile; K chunks rotated (x-half 8..15 first),
//       spin on g_gather_done before prefetching the first mean chunk.
// Dispatch is in ascending blockIdx order -> all gather blocks are resident
// or done before any GEMM block starts -> spin is deadlock-free.
// ---------------------------------------------------------------------------
__global__ __launch_bounds__(256, 3)
void fused_kernel(const float* __restrict__ bias, float* __restrict__ out)
{
    extern __shared__ __align__(128) char smem[];
    const int bb  = blockIdx.x;
    const int tid = threadIdx.x;

    if (bb < G_BLKS) {
        // ================= gather blocks =================
        const int gw   = bb * 8 + (tid >> 5);
        const int lane = tid & 31;
        const int node  = gw >> 1;
        const int slice = gw & 1;
        int deg = g_cursor[node];
        if (deg > DEGCAP) deg = DEGCAP;
        const int* el = g_elist + (size_t)node * DEGCAP;

        const __half* xb = g_Ah + DDIM + slice * 256 + lane * 8;
        float acc[8];
#pragma unroll
        for (int j = 0; j < 8; ++j) acc[j] = 0.0f;

        int e = 0;
        for (; e + 4 <= deg; e += 4) {
            const int4 idx = *(const int4*)(el + e);
            const uint4 v0 = *(const uint4*)(xb + (size_t)idx.x * KTOT);
            const uint4 v1 = *(const uint4*)(xb + (size_t)idx.y * KTOT);
            const uint4 v2 = *(const uint4*)(xb + (size_t)idx.z * KTOT);
            const uint4 v3 = *(const uint4*)(xb + (size_t)idx.w * KTOT);
            const __half2* h0 = (const __half2*)&v0;
            const __half2* h1 = (const __half2*)&v1;
            const __half2* h2 = (const __half2*)&v2;
            const __half2* h3 = (const __half2*)&v3;
#pragma unroll
            for (int j = 0; j < 4; ++j) {
                float2 f0 = __half22float2(h0[j]);
                float2 f1 = __half22float2(h1[j]);
                float2 f2 = __half22float2(h2[j]);
                float2 f3 = __half22float2(h3[j]);
                acc[2 * j]     += (f0.x + f1.x) + (f2.x + f3.x);
                acc[2 * j + 1] += (f0.y + f1.y) + (f2.y + f3.y);
            }
        }
        for (; e < deg; ++e) {
            const int src = el[e];
            const uint4 v = *(const uint4*)(xb + (size_t)src * KTOT);
            const __half2* h = (const __half2*)&v;
#pragma unroll
            for (int j = 0; j < 4; ++j) {
                const float2 f = __half22float2(h[j]);
                acc[2 * j]     += f.x;
                acc[2 * j + 1] += f.y;
            }
        }
        const float invd = 1.0f / fmaxf((float)deg, 1.0f);
        __half2 o[4];
#pragma unroll
        for (int j = 0; j < 4; ++j)
            o[j] = __floats2half2_rn(acc[2 * j] * invd, acc[2 * j + 1] * invd);
        *(uint4*)(g_Ah + (size_t)node * KTOT + slice * 256 + lane * 8) =
            *(const uint4*)o;

        // reset this block's cursor entries (both slices already read deg)
        __syncthreads();
        if (tid < 4) g_cursor[bb * 4 + tid] = 0;
        // signal completion (ensure mean writes visible first)
        __threadfence();
        __syncthreads();
        if (tid == 0) atomicAdd(&g_gather_done, 1);
        return;
    }

    // ================= GEMM blocks =================
    const uint32_t smem_base = smem_u32(smem);
    const int b2    = bb - G_BLKS;
    const int wid   = tid >> 5;
    const int lane  = tid & 31;
    const int warpM = wid >> 2;
    const int warpN = wid & 3;
    const int mBase = (b2 >> 2) * MTILE;
    const int nBase = (b2 & 3) * 128;

    float acc[3][4][4];
#pragma unroll
    for (int i = 0; i < 3; ++i)
#pragma unroll
        for (int j = 0; j < 4; ++j)
#pragma unroll
            for (int r = 0; r < 4; ++r) acc[i][j][r] = 0.0f;

    // chunk rotation: logical s -> physical chunk (s+8)&15  (x-half first)
#pragma unroll
    for (int s = 0; s < NSTAGE; ++s) {
        load_stage(smem_base + s * STAGE_BYTES, (((s + 8) & 15) * KCHUNK),
                   mBase, nBase, tid);
        CP_COMMIT();
    }

    const int matA = lane >> 3;
    const int rA   = lane & 7;
    const int rowA_off = ((matA & 1) << 3) + rA;
    const int chA_off  = matA >> 1;
    const int rowB_off = ((matA >> 1) << 3) + rA;
    const int chB_off  = matA & 1;

    for (int s = 0; s < KSTEPS; ++s) {
        CP_WAIT();
        __syncthreads();

        const uint32_t st  = smem_base + (s % NSTAGE) * STAGE_BYTES;
        const uint32_t sAh = st + OFF_AH;
        const uint32_t sBh = st + OFF_BH;

#pragma unroll
        for (int kk = 0; kk < 4; ++kk) {
            uint32_t ah[3][4], bh[4][2];
#pragma unroll
            for (int mt = 0; mt < 3; ++mt) {
                const int row = warpM * 48 + mt * 16 + rowA_off;
                const int ch  = kk * 2 + chA_off;
                const uint32_t a = row * ROWB + ch * 16;
                LDMX4(ah[mt][0], ah[mt][1], ah[mt][2], ah[mt][3], sAh + a);
            }
#pragma unroll
            for (int p = 0; p < 2; ++p) {
                const int row = warpN * 32 + p * 16 + rowB_off;
                const int ch  = kk * 2 + chB_off;
                const uint32_t a = row * ROWB + ch * 16;
                LDMX4(bh[2*p][0], bh[2*p][1], bh[2*p+1][0], bh[2*p+1][1], sBh + a);
            }
#pragma unroll
            for (int mt = 0; mt < 3; ++mt)
#pragma unroll
                for (int nt = 0; nt < 4; ++nt)
                    mma_fp16(acc[mt][nt], ah[mt], bh[nt]);
        }

        __syncthreads();
        if (s + NSTAGE < KSTEPS) {
            // next prefetch is chunk (s+NSTAGE+8)&15; the first MEAN chunk
            // (phys 0) appears at s == 8-NSTAGE: wait for all gather blocks.
            if (s == 8 - NSTAGE) {
                if (tid == 0) {
                    while (atomicAdd(&g_gather_done, 0) < G_BLKS) { }
                }
                __syncthreads();
            }
            load_stage(st, (((s + NSTAGE + 8) & 15) * KCHUNK),
                       mBase, nBase, tid);
        }
        CP_COMMIT();
    }

    const int colLane = (lane & 3) * 2;
    const int rowLane = lane >> 2;
#pragma unroll
    for (int mt = 0; mt < 3; ++mt) {
#pragma unroll
        for (int nt = 0; nt < 4; ++nt) {
            const int col = nBase + warpN * 32 + nt * 8 + colLane;
            const float b0 = __ldg(bias + col);
            const float b1 = __ldg(bias + col + 1);
#pragma unroll
            for (int half = 0; half < 2; ++half) {
                const int row = mBase + warpM * 48 + mt * 16 + rowLane + half * 8;
                if (row < NNODES) {
                    float h0 = acc[mt][nt][half * 2 + 0] + b0;
                    float h1 = acc[mt][nt][half * 2 + 1] + b1;
                    float2 o;
                    o.x = h0 / (1.0f + __expf(-h0));
                    o.y = h1 / (1.0f + __expf(-h1));
                    *(float2*)(out + (size_t)row * DDIM + col) = o;
                }
            }
        }
    }
}

// ---------------------------------------------------------------------------
extern "C" void kernel_launch(void* const* d_in, const int* in_sizes, int n_in,
                              void* d_out, int out_size) {
    const float* x  = nullptr;
    const void*  ei = nullptr;
    const float* Wl = nullptr;
    const float* Wr = nullptr;
    const float* b  = nullptr;

    for (int i = 0; i < n_in; ++i) {
        const int s = in_sizes[i];
        if (s == NNODES * DDIM)      x  = (const float*)d_in[i];
        else if (s == 2 * NEDGES)    ei = d_in[i];
        else if (s == DDIM * DDIM) { if (!Wl) Wl = (const float*)d_in[i];
                                     else     Wr = (const float*)d_in[i]; }
        else if (s == DDIM)          b  = (const float*)d_in[i];
    }
    float* out = (float*)d_out;
    (void)out_size;

    cudaFuncSetAttribute(fused_kernel,
        cudaFuncAttributeMaxDynamicSharedMemorySize, SMEM_TOTAL);

    prep_kernel<<<P_TOTAL, 256>>>(ei, x, Wl, Wr);
    fused_kernel<<<F_TOTAL, 256, SMEM_TOTAL>>>(b, out);
}

// round 17
// speedup vs baseline: 1.1286x; 1.1286x over previous
#include <cuda_runtime.h>
#include <cuda_fp16.h>
#include <math.h>
#include <cstdint>

#define NNODES 10000
#define NEDGES 160000
#define DDIM   512
#define KTOT   1024
#define MTILE  96
#define MTILES 105
#define MPAD   (MTILE * MTILES)   // 10080
#define KCHUNK 64
#define NSTAGE 2
#define KSTEPS (KTOT / KCHUNK)    // 16
#define DEGCAP 128

// smem rows: 64 fp16 = 128B data + 16B pad -> stride 144B (conflict-free LDSM)
#define ROWB    144
#define A_TILEB (MTILE * ROWB)            // 13824
#define B_TILEB (128 * ROWB)              // 18432
#define OFF_AH  0
#define OFF_BH  (A_TILEB)
#define STAGE_BYTES (A_TILEB + B_TILEB)       // 32256
#define SMEM_TOTAL  (NSTAGE * STAGE_BYTES)    // 64512 -> 3 CTAs/SM

// ---------------------------------------------------------------------------
// Device scratch
// ---------------------------------------------------------------------------
__device__ int    g_cursor[NNODES];
__device__ int    g_elist[(size_t)NNODES * DEGCAP];
__device__ __half g_Ah[(size_t)MPAD * KTOT];
__device__ __half g_Bh[(size_t)DDIM * KTOT];    // [n][k]

// ---------------------------------------------------------------------------
// helpers
// ---------------------------------------------------------------------------
__device__ __forceinline__ uint32_t smem_u32(const void* p) {
    uint32_t a;
    asm("{ .reg .u64 t; cvta.to.shared.u64 t, %1; cvt.u32.u64 %0, t; }"
        : "=r"(a) : "l"(p));
    return a;
}
#define CP16(sm, gm) \
    asm volatile("cp.async.cg.shared.global [%0], [%1], 16;" :: "r"(sm), "l"(gm))
#define CP_COMMIT() asm volatile("cp.async.commit_group;" ::: "memory")
#define CP_WAIT()   asm volatile("cp.async.wait_group 1;"  ::: "memory")

#define LDMX4(r0, r1, r2, r3, addr) \
    asm volatile("ldmatrix.sync.aligned.m8n8.x4.shared.b16 {%0,%1,%2,%3}, [%4];" \
        : "=r"(r0), "=r"(r1), "=r"(r2), "=r"(r3) : "r"(addr))

__device__ __forceinline__ void mma_fp16(float* c, const uint32_t* a,
                                         const uint32_t* b) {
    asm volatile(
        "mma.sync.aligned.m16n8k16.row.col.f32.f16.f16.f32 "
        "{%0,%1,%2,%3}, {%4,%5,%6,%7}, {%8,%9}, {%0,%1,%2,%3};"
        : "+f"(c[0]), "+f"(c[1]), "+f"(c[2]), "+f"(c[3])
        : "r"(a[0]), "r"(a[1]), "r"(a[2]), "r"(a[3]), "r"(b[0]), "r"(b[1]));
}

__device__ __forceinline__ void store_h4(float4 v, __half* p) {
    *(__half2*)(p)     = __floats2half2_rn(v.x, v.y);
    *(__half2*)(p + 2) = __floats2half2_rn(v.z, v.w);
}

// ---------------------------------------------------------------------------
// Kernel 1: fused prep — block-range dispatch:
//   [0, 625)        CSR bucket fill (atomics)
//   [625, 3125)     x -> fp16, ILP=2 per thread (two independent float4 loads)
//   [3125, 3165)    zero pad rows [NNODES, MPAD), ILP=2
//   [3165, 3677)    B transpose (fp16)
// ---------------------------------------------------------------------------
#define P_FILL_BLKS 625
#define P_X_BLKS    2500
#define P_PAD_BLKS  40
#define P_B_BLKS    512
#define P_TOTAL (P_FILL_BLKS + P_X_BLKS + P_PAD_BLKS + P_B_BLKS)

__global__ __launch_bounds__(256) void prep_kernel(
    const void* __restrict__ ei,
    const float* __restrict__ x,
    const float* __restrict__ Wl, const float* __restrict__ Wr)
{
    __shared__ float ts[32][33];
    const int bb  = blockIdx.x;
    const int tid = threadIdx.x;

    if (bb < P_FILL_BLKS) {
        const int e = bb * 256 + tid;
        if (e >= NEDGES) return;
        const int* ei32 = (const int*)ei;
        int acc = 0;
#pragma unroll
        for (int j = 1; j < 32; j += 2) acc |= __ldg(ei32 + j);
        int src, dst;
        if (acc == 0) {
            const long long* e64 = (const long long*)ei;
            src = (int)e64[e];
            dst = (int)e64[NEDGES + e];
        } else {
            src = ei32[e];
            dst = ei32[NEDGES + e];
        }
        if ((unsigned)src >= NNODES || (unsigned)dst >= NNODES) return;
        const int pos = atomicAdd(&g_cursor[dst], 1);
        if (pos < DEGCAP) g_elist[(size_t)dst * DEGCAP + pos] = src;
    } else if (bb < P_FILL_BLKS + P_X_BLKS) {
        // two independent float4 loads per thread (MLP=2), then two stores
        const int i0 = (bb - P_FILL_BLKS) * 512 + tid;
        const int i1 = i0 + 256;
        const int r0 = i0 >> 7, g0 = (i0 & 127) * 4;
        const int r1 = i1 >> 7, g1 = (i1 & 127) * 4;
        const float4 v0 = *(const float4*)(x + (size_t)r0 * DDIM + g0);
        const float4 v1 = *(const float4*)(x + (size_t)r1 * DDIM + g1);
        store_h4(v0, g_Ah + (size_t)r0 * KTOT + DDIM + g0);
        store_h4(v1, g_Ah + (size_t)r1 * KTOT + DDIM + g1);
    } else if (bb < P_FILL_BLKS + P_X_BLKS + P_PAD_BLKS) {
        const int i0 = (bb - P_FILL_BLKS - P_X_BLKS) * 512 + tid;
        const int i1 = i0 + 256;
        const int row0 = NNODES + (i0 >> 8), g0 = (i0 & 255) * 4;
        const int row1 = NNODES + (i1 >> 8), g1 = (i1 & 255) * 4;
        *(uint64_t*)(g_Ah + (size_t)row0 * KTOT + g0) = 0ull;
        *(uint64_t*)(g_Ah + (size_t)row1 * KTOT + g1) = 0ull;
    } else {
        const int tb = bb - P_FILL_BLKS - P_X_BLKS - P_PAD_BLKS;
        const int k0 = (tb >> 4) * 32;
        const int n0 = (tb & 15) * 32;
        const int r  = tid >> 3;
        const int c  = (tid & 7) * 4;

        const int k = k0 + r;
        const float4 v = (k < DDIM)
            ? *(const float4*)(Wl + (size_t)k * DDIM + n0 + c)
            : *(const float4*)(Wr + (size_t)(k - DDIM) * DDIM + n0 + c);
        ts[r][c + 0] = v.x; ts[r][c + 1] = v.y;
        ts[r][c + 2] = v.z; ts[r][c + 3] = v.w;
        __syncthreads();

        const int n = n0 + r;
        float4 w = make_float4(ts[c][r], ts[c + 1][r], ts[c + 2][r], ts[c + 3][r]);
        store_h4(w, g_Bh + (size_t)n * KTOT + k0 + c);
    }
}

// ---------------------------------------------------------------------------
// Kernel 2: gather + mean from the fp16 x-copy (L2-bandwidth-floor bound).
// One warp per (node, 256-col slice); edge loop unrolled x4.
// ---------------------------------------------------------------------------
__global__ __launch_bounds__(256) void gather_kernel() {
    const int gw   = blockIdx.x * 8 + (threadIdx.x >> 5);
    const int lane = threadIdx.x & 31;
    if (gw >= NNODES * 2) return;
    const int node  = gw >> 1;
    const int slice = gw & 1;
    int deg = g_cursor[node];
    if (deg > DEGCAP) deg = DEGCAP;
    const int* el = g_elist + (size_t)node * DEGCAP;

    const __half* xb = g_Ah + DDIM + slice * 256 + lane * 8;
    float acc[8];
#pragma unroll
    for (int j = 0; j < 8; ++j) acc[j] = 0.0f;

    int e = 0;
    for (; e + 4 <= deg; e += 4) {
        const int4 idx = *(const int4*)(el + e);
        const uint4 v0 = *(const uint4*)(xb + (size_t)idx.x * KTOT);
        const uint4 v1 = *(const uint4*)(xb + (size_t)idx.y * KTOT);
        const uint4 v2 = *(const uint4*)(xb + (size_t)idx.z * KTOT);
        const uint4 v3 = *(const uint4*)(xb + (size_t)idx.w * KTOT);
        const __half2* h0 = (const __half2*)&v0;
        const __half2* h1 = (const __half2*)&v1;
        const __half2* h2 = (const __half2*)&v2;
        const __half2* h3 = (const __half2*)&v3;
#pragma unroll
        for (int j = 0; j < 4; ++j) {
            float2 f0 = __half22float2(h0[j]);
            float2 f1 = __half22float2(h1[j]);
            float2 f2 = __half22float2(h2[j]);
            float2 f3 = __half22float2(h3[j]);
            acc[2 * j]     += (f0.x + f1.x) + (f2.x + f3.x);
            acc[2 * j + 1] += (f0.y + f1.y) + (f2.y + f3.y);
        }
    }
    for (; e < deg; ++e) {
        const int src = el[e];
        const uint4 v = *(const uint4*)(xb + (size_t)src * KTOT);
        const __half2* h = (const __half2*)&v;
#pragma unroll
        for (int j = 0; j < 4; ++j) {
            const float2 f = __half22float2(h[j]);
            acc[2 * j]     += f.x;
            acc[2 * j + 1] += f.y;
        }
    }
    const float invd = 1.0f / fmaxf((float)deg, 1.0f);
    __half2 o[4];
#pragma unroll
    for (int j = 0; j < 4; ++j)
        o[j] = __floats2half2_rn(acc[2 * j] * invd, acc[2 * j + 1] * invd);
    *(uint4*)(g_Ah + (size_t)node * KTOT + slice * 256 + lane * 8) =
        *(const uint4*)o;
}

// ---------------------------------------------------------------------------
// Kernel 3: fp16 HMMA GEMM, 96x128 tile, KCHUNK=64, 2-stage cp.async,
//           3 CTAs/SM (24 warps), __expf swish epilogue
// ---------------------------------------------------------------------------
__device__ __forceinline__ void load_stage(
    uint32_t st, int k0, int mBase, int nBase, int tid)
{
    // 1792 16B-chunks: Ah 768 | Bh 1024 -> exactly 7 per thread
#pragma unroll
    for (int i = 0; i < 7; ++i) {
        const int c = tid + i * 256;
        uint32_t sm;
        const __half* gp;
        if (c < 768) {
            const int row = c >> 3;
            const int ch  = c & 7;
            sm = st + OFF_AH + row * ROWB + ch * 16;
            gp = g_Ah + (size_t)(mBase + row) * KTOT + k0 + ch * 8;
        } else {
            const int d   = c - 768;
            const int row = d >> 3;
            const int ch  = d & 7;
            sm = st + OFF_BH + row * ROWB + ch * 16;
            gp = g_Bh + (size_t)(nBase + row) * KTOT + k0 + ch * 8;
        }
        CP16(sm, gp);
    }
}

__global__ __launch_bounds__(256, 3)
void gemm_kernel(const float* __restrict__ bias, float* __restrict__ out)
{
    extern __shared__ __align__(128) char smem[];
    const uint32_t smem_base = smem_u32(smem);
    const int tid   = threadIdx.x;
    const int wid   = tid >> 5;
    const int lane  = tid & 31;
    const int warpM = wid >> 2;
    const int warpN = wid & 3;
    const int mBase = blockIdx.x * MTILE;
    const int nBase = blockIdx.y * 128;

    // reset CSR cursors for the next graph replay
    if (blockIdx.y == 0 && blockIdx.x < 40) {
        const int i = blockIdx.x * 256 + tid;
        if (i < NNODES) g_cursor[i] = 0;
    }

    float acc[3][4][4];
#pragma unroll
    for (int i = 0; i < 3; ++i)
#pragma unroll
        for (int j = 0; j < 4; ++j)
#pragma unroll
            for (int r = 0; r < 4; ++r) acc[i][j][r] = 0.0f;

#pragma unroll
    for (int s = 0; s < NSTAGE; ++s) {
        load_stage(smem_base + s * STAGE_BYTES, s * KCHUNK, mBase, nBase, tid);
        CP_COMMIT();
    }

    const int matA = lane >> 3;
    const int rA   = lane & 7;
    const int rowA_off = ((matA & 1) << 3) + rA;
    const int chA_off  = matA >> 1;
    const int rowB_off = ((matA >> 1) << 3) + rA;
    const int chB_off  = matA & 1;

    for (int s = 0; s < KSTEPS; ++s) {
        CP_WAIT();
        __syncthreads();

        const uint32_t st  = smem_base + (s % NSTAGE) * STAGE_BYTES;
        const uint32_t sAh = st + OFF_AH;
        const uint32_t sBh = st + OFF_BH;

#pragma unroll
        for (int kk = 0; kk < 4; ++kk) {
            uint32_t ah[3][4], bh[4][2];
#pragma unroll
            for (int mt = 0; mt < 3; ++mt) {
                const int row = warpM * 48 + mt * 16 + rowA_off;
                const int ch  = kk * 2 + chA_off;
                const uint32_t a = row * ROWB + ch * 16;
                LDMX4(ah[mt][0], ah[mt][1], ah[mt][2], ah[mt][3], sAh + a);
            }
#pragma unroll
            for (int p = 0; p < 2; ++p) {
                const int row = warpN * 32 + p * 16 + rowB_off;
                const int ch  = kk * 2 + chB_off;
                const uint32_t a = row * ROWB + ch * 16;
                LDMX4(bh[2*p][0], bh[2*p][1], bh[2*p+1][0], bh[2*p+1][1], sBh + a);
            }
#pragma unroll
            for (int mt = 0; mt < 3; ++mt)
#pragma unroll
                for (int nt = 0; nt < 4; ++nt)
                    mma_fp16(acc[mt][nt], ah[mt], bh[nt]);
        }

        __syncthreads();
        if (s + NSTAGE < KSTEPS)
            load_stage(st, (s + NSTAGE) * KCHUNK, mBase, nBase, tid);
        CP_COMMIT();
    }

    const int colLane = (lane & 3) * 2;
    const int rowLane = lane >> 2;
#pragma unroll
    for (int mt = 0; mt < 3; ++mt) {
#pragma unroll
        for (int nt = 0; nt < 4; ++nt) {
            const int col = nBase + warpN * 32 + nt * 8 + colLane;
            const float b0 = __ldg(bias + col);
            const float b1 = __ldg(bias + col + 1);
#pragma unroll
            for (int half = 0; half < 2; ++half) {
                const int row = mBase + warpM * 48 + mt * 16 + rowLane + half * 8;
                if (row < NNODES) {
                    float h0 = acc[mt][nt][half * 2 + 0] + b0;
                    float h1 = acc[mt][nt][half * 2 + 1] + b1;
                    float2 o;
                    o.x = h0 / (1.0f + __expf(-h0));
                    o.y = h1 / (1.0f + __expf(-h1));
                    *(float2*)(out + (size_t)row * DDIM + col) = o;
                }
            }
        }
    }
}

// ---------------------------------------------------------------------------
extern "C" void kernel_launch(void* const* d_in, const int* in_sizes, int n_in,
                              void* d_out, int out_size) {
    const float* x  = nullptr;
    const void*  ei = nullptr;
    const float* Wl = nullptr;
    const float* Wr = nullptr;
    const float* b  = nullptr;

    for (int i = 0; i < n_in; ++i) {
        const int s = in_sizes[i];
        if (s == NNODES * DDIM)      x  = (const float*)d_in[i];
        else if (s == 2 * NEDGES)    ei = d_in[i];
        else if (s == DDIM * DDIM) { if (!Wl) Wl = (const float*)d_in[i];
                                     else     Wr = (const float*)d_in[i]; }
        else if (s == DDIM)          b  = (const float*)d_in[i];
    }
    float* out = (float*)d_out;
    (void)out_size;

    cudaFuncSetAttribute(gemm_kernel,
        cudaFuncAttributeMaxDynamicSharedMemorySize, SMEM_TOTAL);

    prep_kernel<<<P_TOTAL, 256>>>(ei, x, Wl, Wr);
    gather_kernel<<<(NNODES * 2 + 7) / 8, 256>>>();

    dim3 grid(MTILES, 4);
    gemm_kernel<<<grid, 256, SMEM_TOTAL>>>(b, out);
}